// round 6
// baseline (speedup 1.0000x reference)
#include <cuda_runtime.h>

#define HID   2048
#define NEXP  64
#define TOPK  8
#define TPB   64          // tokens per block
#define KC    64          // k-chunk
#define NCHUNK (HID/KC)   // 32
#define THREADS 256
#define PAD   68          // smem row stride (floats)
#define NTOK  16384
#define RS_H  0.022097086912079612f   // 1/sqrt(2048)
#define EPSV  1e-6f

// packed fp32x2 ops (sm_103a) — each half rounds identically to the scalar op
#define MUL2(d,a,b)   asm("mul.rn.f32x2 %0, %1, %2;"     : "=l"(d) : "l"(a), "l"(b))
#define FMA2(d,a,b,c) asm("fma.rn.f32x2 %0, %1, %2, %3;" : "=l"(d) : "l"(a), "l"(b), "l"(c))
#define ADD2(d,a,b)   asm("add.rn.f32x2 %0, %1, %2;"     : "=l"(d) : "l"(a), "l"(b))
#define DUP2(d,s)     asm("mov.b64 %0, {%1, %1};"        : "=l"(d) : "r"(s))

__global__ void init_counts_kernel(float* __restrict__ out) {
    out[2 * NTOK * TOPK + threadIdx.x] = 0.0f;
}

__global__ __launch_bounds__(THREADS, 2)
void gemma4_router_kernel(const float* __restrict__ hs,
                          const float* __restrict__ scale,
                          const float* __restrict__ pw,
                          const float* __restrict__ pes,
                          float* __restrict__ out) {
    __shared__ float xs[TPB][PAD];      // token tile (reused for logits in phase C)
    __shared__ float ws_t[KC][PAD];     // TRANSPOSED weight tile: [k][expert ^ swz(k)]
    __shared__ float ssq_s[TPB];
    __shared__ float pes_s[NEXP];
    __shared__ int   hist_s[NEXP];

    const int tid  = threadIdx.x;
    const int tok0 = blockIdx.x * TPB;

    if (tid < NEXP) { pes_s[tid] = pes[tid]; hist_s[tid] = 0; }

    // staging mapping (identical to round-2)
    const int g  = tid >> 4;   // 0..15
    const int c4 = tid & 15;   // 0..15

    // GEMM mapping: 8 expert-cols x 32 token-rows
    const int tcol = tid & 7;          // experts ee0..ee0+7
    const int trow = tid >> 3;         // token pair trow*2, trow*2+1
    const int ee0  = tcol * 8;
    const int t0   = trow * 2;
    const int t1   = t0 + 1;

    // ---- software-pipelined load staging ----
    float4 xr[4], wr[4], sc;
    float  ssq[4] = {0.f, 0.f, 0.f, 0.f};

    {
        const float* hp = hs + (size_t)tok0 * HID + c4 * 4;
        const float* wp = pw + c4 * 4;
        #pragma unroll
        for (int i = 0; i < 4; i++) {
            int r = g + 16 * i;
            xr[i] = *(const float4*)(hp + (size_t)r * HID);
            wr[i] = *(const float4*)(wp + (size_t)r * HID);
        }
        sc = *(const float4*)(scale + c4 * 4);
    }

    // accumulators: 2 tokens x 4 expert-pairs, each half = one full expert chain
    unsigned long long acc[2][4];
    #pragma unroll
    for (int a = 0; a < 2; a++)
        #pragma unroll
        for (int p = 0; p < 4; p++) acc[a][p] = 0ull;

    for (int ch = 0; ch < NCHUNK; ch++) {
        // commit staged regs to smem; fold scale*H^-0.5 into W exactly as round-2
        #pragma unroll
        for (int i = 0; i < 4; i++) {
            int r = g + 16 * i;      // token row (x) / expert row (w)
            *(float4*)&xs[r][c4 * 4] = xr[i];
            ssq[i] += xr[i].x * xr[i].x + xr[i].y * xr[i].y
                    + xr[i].z * xr[i].z + xr[i].w * xr[i].w;
            float wv0 = wr[i].x * sc.x * RS_H;
            float wv1 = wr[i].y * sc.y * RS_H;
            float wv2 = wr[i].z * sc.z * RS_H;
            float wv3 = wr[i].w * sc.w * RS_H;
            // transposed store: ws_t[k][e ^ ((k>>2)<<2)], k = c4*4+j -> (k>>2)=c4
            int colx = r ^ (c4 << 2);
            ws_t[c4 * 4 + 0][colx] = wv0;
            ws_t[c4 * 4 + 1][colx] = wv1;
            ws_t[c4 * 4 + 2][colx] = wv2;
            ws_t[c4 * 4 + 3][colx] = wv3;
        }
        __syncthreads();

        // prefetch next chunk (overlaps with FMA loop)
        if (ch + 1 < NCHUNK) {
            const float* hpn = hs + (size_t)tok0 * HID + (ch + 1) * KC + c4 * 4;
            const float* wpn = pw + (ch + 1) * KC + c4 * 4;
            #pragma unroll
            for (int i = 0; i < 4; i++) {
                int r = g + 16 * i;
                xr[i] = *(const float4*)(hpn + (size_t)r * HID);
                wr[i] = *(const float4*)(wpn + (size_t)r * HID);
            }
            sc = *(const float4*)(scale + (ch + 1) * KC + c4 * 4);
        }

        // GEMM: per 4k group, per expert-half: T = mul,fma,fma,fma; acc += T
        // (mirrors round-2's FMUL+3xFFMA+FADD contraction, bit-identically)
        #pragma unroll
        for (int k4 = 0; k4 < KC; k4 += 4) {
            float4 xa4 = *(const float4*)&xs[t0][k4];
            float4 xb4 = *(const float4*)&xs[t1][k4];
            float xaf[4] = {xa4.x, xa4.y, xa4.z, xa4.w};
            float xbf[4] = {xb4.x, xb4.y, xb4.z, xb4.w};
            unsigned long long T[2][4];
            #pragma unroll
            for (int kk = 0; kk < 4; kk++) {
                int k   = k4 + kk;
                int col = ee0 ^ ((k >> 2) << 2);
                ulonglong2 wlo = *(const ulonglong2*)&ws_t[k][col];       // experts e0,e1|e2,e3
                ulonglong2 whi = *(const ulonglong2*)&ws_t[k][col ^ 4];   // experts e4,e5|e6,e7
                unsigned long long xda, xdb;
                DUP2(xda, __float_as_uint(xaf[kk]));
                DUP2(xdb, __float_as_uint(xbf[kk]));
                if (kk == 0) {
                    MUL2(T[0][0], xda, wlo.x); MUL2(T[0][1], xda, wlo.y);
                    MUL2(T[0][2], xda, whi.x); MUL2(T[0][3], xda, whi.y);
                    MUL2(T[1][0], xdb, wlo.x); MUL2(T[1][1], xdb, wlo.y);
                    MUL2(T[1][2], xdb, whi.x); MUL2(T[1][3], xdb, whi.y);
                } else {
                    FMA2(T[0][0], xda, wlo.x, T[0][0]); FMA2(T[0][1], xda, wlo.y, T[0][1]);
                    FMA2(T[0][2], xda, whi.x, T[0][2]); FMA2(T[0][3], xda, whi.y, T[0][3]);
                    FMA2(T[1][0], xdb, wlo.x, T[1][0]); FMA2(T[1][1], xdb, wlo.y, T[1][1]);
                    FMA2(T[1][2], xdb, whi.x, T[1][2]); FMA2(T[1][3], xdb, whi.y, T[1][3]);
                }
            }
            #pragma unroll
            for (int a = 0; a < 2; a++)
                #pragma unroll
                for (int p = 0; p < 4; p++)
                    ADD2(acc[a][p], acc[a][p], T[a][p]);
        }
        __syncthreads();
    }

    // ---- per-token sum-of-squares reduction (identical to round-2) ----
    #pragma unroll
    for (int i = 0; i < 4; i++) {
        float v = ssq[i];
        v += __shfl_xor_sync(0xffffffffu, v, 1);
        v += __shfl_xor_sync(0xffffffffu, v, 2);
        v += __shfl_xor_sync(0xffffffffu, v, 4);
        v += __shfl_xor_sync(0xffffffffu, v, 8);
        if (c4 == 0) ssq_s[g + 16 * i] = v;
    }
    __syncthreads();

    // ---- apply RMS factor, write logits into xs ----
    float f0 = rsqrtf(ssq_s[t0] * (1.0f / HID) + EPSV);
    float f1 = rsqrtf(ssq_s[t1] * (1.0f / HID) + EPSV);
    __syncthreads();
    #pragma unroll
    for (int p = 0; p < 4; p++) {
        float2 v0 = *reinterpret_cast<float2*>(&acc[0][p]);
        float2 v1 = *reinterpret_cast<float2*>(&acc[1][p]);
        xs[t0][ee0 + 2 * p]     = v0.x * f0;
        xs[t0][ee0 + 2 * p + 1] = v0.y * f0;
        xs[t1][ee0 + 2 * p]     = v1.x * f1;
        xs[t1][ee0 + 2 * p + 1] = v1.y * f1;
    }
    __syncthreads();

    // ---- phase C: softmax + top-8 (one warp handles 8 tokens) ----
    const int wid = tid >> 5, lane = tid & 31;
    for (int t = wid * 8; t < wid * 8 + 8; t++) {
        float v0 = xs[t][lane];
        float v1 = xs[t][lane + 32];

        float m = fmaxf(v0, v1);
        #pragma unroll
        for (int s = 16; s > 0; s >>= 1)
            m = fmaxf(m, __shfl_xor_sync(0xffffffffu, m, s));

        float p0 = expf(v0 - m);
        float p1 = expf(v1 - m);
        float sum = p0 + p1;
        #pragma unroll
        for (int s = 16; s > 0; s >>= 1)
            sum += __shfl_xor_sync(0xffffffffu, sum, s);
        float inv = 1.0f / sum;
        p0 *= inv; p1 *= inv;

        float wsum = 0.f;
        float myv = 0.f; int myi = 0;
        #pragma unroll
        for (int r = 0; r < TOPK; r++) {
            float bv = p0; int bi = lane;
            if (p1 > bv) { bv = p1; bi = lane + 32; }
            #pragma unroll
            for (int s = 16; s > 0; s >>= 1) {
                float ov = __shfl_xor_sync(0xffffffffu, bv, s);
                int   oi = __shfl_xor_sync(0xffffffffu, bi, s);
                if (ov > bv || (ov == bv && oi < bi)) { bv = ov; bi = oi; }
            }
            wsum += bv;
            if (lane == r) { myv = bv; myi = bi; }
            if (bi == lane)            p0 = -1.f;
            else if (bi == lane + 32)  p1 = -1.f;
        }

        if (lane < TOPK) {
            int gt = tok0 + t;
            out[(size_t)gt * TOPK + lane] = myv / wsum * pes_s[myi];
            out[(size_t)NTOK * TOPK + (size_t)gt * TOPK + lane] = (float)myi;
            atomicAdd(&hist_s[myi], 1);
        }
    }

    __syncthreads();
    if (tid < NEXP)
        atomicAdd(&out[2 * NTOK * TOPK + tid], (float)hist_s[tid]);
}

extern "C" void kernel_launch(void* const* d_in, const int* in_sizes, int n_in,
                              void* d_out, int out_size) {
    const float* hs    = (const float*)d_in[0];   // [4,4096,2048] f32
    const float* scale = (const float*)d_in[1];   // [2048] f32
    const float* pw    = (const float*)d_in[2];   // [64,2048] f32
    const float* pes   = (const float*)d_in[3];   // [64] f32
    float* out = (float*)d_out;                   // weights | indices | counts

    init_counts_kernel<<<1, NEXP>>>(out);
    gemma4_router_kernel<<<NTOK / TPB, THREADS>>>(hs, scale, pw, pes, out);
}

// round 8
// speedup vs baseline: 1.6403x; 1.6403x over previous
#include <cuda_runtime.h>

#define HID   2048
#define NEXP  64
#define TOPK  8
#define TPB   64
#define KC    64
#define NCHUNK 32
#define THREADS 256
#define SX    68          // smem row stride (floats) -> 17 quads, odd
#define NTOK  16384
#define RS_H  0.022097086912079612f   // 1/sqrt(2048)
#define EPSV  1e-6f

// folded (scale * RS_H), transposed [k][col], granule-remapped weights
__device__ float w_t_g[HID * NEXP];

#define MUL2(d,a,b)   asm("mul.rn.f32x2 %0, %1, %2;"     : "=l"(d) : "l"(a), "l"(b))
#define FMA2(d,a,b,c) asm("fma.rn.f32x2 %0, %1, %2, %3;" : "=l"(d) : "l"(a), "l"(b), "l"(c))
#define ADD2(d,a,b)   asm("add.rn.f32x2 %0, %1, %2;"     : "=l"(d) : "l"(a), "l"(b))
#define DUP2(d,s)     asm("mov.b64 %0, {%1, %1};"        : "=l"(d) : "r"(s))

// prep: fold scale into W, transpose to [k][64], remap granule position gq to
// expert-granule ge = ((gq&7)<<1)|(gq>>3); zero the expert-count tail of out.
__global__ void prep_kernel(const float* __restrict__ pw,
                            const float* __restrict__ scale,
                            float* __restrict__ out) {
    int o = blockIdx.x * blockDim.x + threadIdx.x;    // 0..131071
    int c  = o & 63;
    int k  = o >> 6;
    int gq = c >> 2;
    int ge = ((gq & 7) << 1) | (gq >> 3);
    int e  = ge * 4 + (c & 3);
    w_t_g[o] = pw[(size_t)e * HID + k] * scale[k] * RS_H;
    if (o < NEXP) out[2 * NTOK * TOPK + o] = 0.0f;
}

__global__ __launch_bounds__(THREADS, 2)
void gemma4_router_kernel(const float* __restrict__ hs,
                          const float* __restrict__ pes,
                          float* __restrict__ out) {
    __shared__ float xs[TPB][SX];     // token tile [t][k] (reused for logits)
    __shared__ float ws[KC][SX];      // weight tile [k][remapped expert col]
    __shared__ float ssq_s[TPB];
    __shared__ float pes_s[NEXP];
    __shared__ int   hist_s[NEXP];

    const int tid  = threadIdx.x;
    const int tok0 = blockIdx.x * TPB;

    if (tid < NEXP) { pes_s[tid] = pes[tid]; hist_s[tid] = 0; }

    // staging mapping: rows r = g + 16i (i=0..3), float4-col c4
    const int c4 = tid & 15;
    const int g  = tid >> 4;          // 0..15
    // GEMM mapping: experts (ecol*8..+7), tokens t0 = trow*2, t1 = t0+1
    const int ecol = tid & 7;
    const int trow = tid >> 3;        // 0..31
    const int t0   = trow * 2;
    const int t1   = t0 + 1;

    float4 xr[4], wr[4];
    float  ssq[4] = {0.f, 0.f, 0.f, 0.f};

    // ---- initial chunk loads (registers) ----
    {
        const float* hp = hs + (size_t)tok0 * HID + c4 * 4;
        const float* wp = w_t_g + c4 * 4;
        #pragma unroll
        for (int i = 0; i < 4; i++) {
            xr[i] = *(const float4*)(hp + (size_t)(g + 16 * i) * HID);
            wr[i] = *(const float4*)(wp + (size_t)(g + 16 * i) * NEXP);
        }
    }

    // accumulators: 2 tokens x 4 expert-pairs; each 32-bit half = one expert chain
    unsigned long long acc[2][4];
    #pragma unroll
    for (int a = 0; a < 2; a++)
        #pragma unroll
        for (int p = 0; p < 4; p++) acc[a][p] = 0ull;

    for (int ch = 0; ch < NCHUNK; ch++) {
        // commit staged registers to smem (W already folded+remapped by prep)
        #pragma unroll
        for (int i = 0; i < 4; i++) {
            int r = g + 16 * i;
            *(float4*)&xs[r][c4 * 4] = xr[i];
            ssq[i] += xr[i].x * xr[i].x + xr[i].y * xr[i].y
                    + xr[i].z * xr[i].z + xr[i].w * xr[i].w;
            *(float4*)&ws[r][c4 * 4] = wr[i];
        }
        __syncthreads();

        // prefetch next chunk (overlaps GEMM)
        if (ch + 1 < NCHUNK) {
            const float* hp = hs + (size_t)tok0 * HID + (ch + 1) * KC + c4 * 4;
            const float* wp = w_t_g + (size_t)(ch + 1) * KC * NEXP + c4 * 4;
            #pragma unroll
            for (int i = 0; i < 4; i++) {
                xr[i] = *(const float4*)(hp + (size_t)(g + 16 * i) * HID);
                wr[i] = *(const float4*)(wp + (size_t)(g + 16 * i) * NEXP);
            }
        }

        // GEMM: per 4k group, per expert-half: T = mul,fma,fma,fma; acc += T
        // (exact round-6 arithmetic — the only contraction that survives top-k)
        #pragma unroll 4
        for (int k4 = 0; k4 < KC; k4 += 4) {
            float4 xa4 = *(const float4*)&xs[t0][k4];
            float4 xb4 = *(const float4*)&xs[t1][k4];
            float xaf[4] = {xa4.x, xa4.y, xa4.z, xa4.w};
            float xbf[4] = {xb4.x, xb4.y, xb4.z, xb4.w};
            unsigned long long T[2][4];
            #pragma unroll
            for (int kk = 0; kk < 4; kk++) {
                // conflict-free: 8 lanes hit 8 distinct quads (granule remap)
                ulonglong2 wlo = *(const ulonglong2*)&ws[k4 + kk][ecol * 4];
                ulonglong2 whi = *(const ulonglong2*)&ws[k4 + kk][(8 + ecol) * 4];
                unsigned long long xda, xdb;
                DUP2(xda, __float_as_uint(xaf[kk]));
                DUP2(xdb, __float_as_uint(xbf[kk]));
                if (kk == 0) {
                    MUL2(T[0][0], xda, wlo.x); MUL2(T[0][1], xda, wlo.y);
                    MUL2(T[0][2], xda, whi.x); MUL2(T[0][3], xda, whi.y);
                    MUL2(T[1][0], xdb, wlo.x); MUL2(T[1][1], xdb, wlo.y);
                    MUL2(T[1][2], xdb, whi.x); MUL2(T[1][3], xdb, whi.y);
                } else {
                    FMA2(T[0][0], xda, wlo.x, T[0][0]); FMA2(T[0][1], xda, wlo.y, T[0][1]);
                    FMA2(T[0][2], xda, whi.x, T[0][2]); FMA2(T[0][3], xda, whi.y, T[0][3]);
                    FMA2(T[1][0], xdb, wlo.x, T[1][0]); FMA2(T[1][1], xdb, wlo.y, T[1][1]);
                    FMA2(T[1][2], xdb, whi.x, T[1][2]); FMA2(T[1][3], xdb, whi.y, T[1][3]);
                }
            }
            #pragma unroll
            for (int a = 0; a < 2; a++)
                #pragma unroll
                for (int p = 0; p < 4; p++)
                    ADD2(acc[a][p], acc[a][p], T[a][p]);
        }
        __syncthreads();
    }

    // ---- per-token sum-of-squares reduction (16 threads share each row) ----
    #pragma unroll
    for (int i = 0; i < 4; i++) {
        float v = ssq[i];
        v += __shfl_xor_sync(0xffffffffu, v, 1);
        v += __shfl_xor_sync(0xffffffffu, v, 2);
        v += __shfl_xor_sync(0xffffffffu, v, 4);
        v += __shfl_xor_sync(0xffffffffu, v, 8);
        if (c4 == 0) ssq_s[g + 16 * i] = v;
    }
    __syncthreads();

    // ---- RMS factor + write logits into xs ----
    float f0 = rsqrtf(ssq_s[t0] * (1.0f / HID) + EPSV);
    float f1 = rsqrtf(ssq_s[t1] * (1.0f / HID) + EPSV);
    __syncthreads();
    #pragma unroll
    for (int p = 0; p < 4; p++) {
        float2 v0 = *reinterpret_cast<float2*>(&acc[0][p]);
        float2 v1 = *reinterpret_cast<float2*>(&acc[1][p]);
        xs[t0][ecol * 8 + 2 * p]     = v0.x * f0;
        xs[t0][ecol * 8 + 2 * p + 1] = v0.y * f0;
        xs[t1][ecol * 8 + 2 * p]     = v1.x * f1;
        xs[t1][ecol * 8 + 2 * p + 1] = v1.y * f1;
    }
    __syncthreads();

    // ---- phase C: softmax + top-8 (one warp handles 8 tokens) ----
    const int wid = tid >> 5, lane = tid & 31;
    for (int t = wid * 8; t < wid * 8 + 8; t++) {
        float v0 = xs[t][lane];
        float v1 = xs[t][lane + 32];

        float m = fmaxf(v0, v1);
        #pragma unroll
        for (int s = 16; s > 0; s >>= 1)
            m = fmaxf(m, __shfl_xor_sync(0xffffffffu, m, s));

        float p0 = expf(v0 - m);
        float p1 = expf(v1 - m);
        float sum = p0 + p1;
        #pragma unroll
        for (int s = 16; s > 0; s >>= 1)
            sum += __shfl_xor_sync(0xffffffffu, sum, s);
        float inv = 1.0f / sum;
        p0 *= inv; p1 *= inv;

        float wsum = 0.f;
        float myv = 0.f; int myi = 0;
        #pragma unroll
        for (int r = 0; r < TOPK; r++) {
            float bv = p0; int bi = lane;
            if (p1 > bv) { bv = p1; bi = lane + 32; }
            #pragma unroll
            for (int s = 16; s > 0; s >>= 1) {
                float ov = __shfl_xor_sync(0xffffffffu, bv, s);
                int   oi = __shfl_xor_sync(0xffffffffu, bi, s);
                if (ov > bv || (ov == bv && oi < bi)) { bv = ov; bi = oi; }
            }
            wsum += bv;
            if (lane == r) { myv = bv; myi = bi; }
            if (bi == lane)            p0 = -1.f;
            else if (bi == lane + 32)  p1 = -1.f;
        }

        if (lane < TOPK) {
            int gt = tok0 + t;
            out[(size_t)gt * TOPK + lane] = myv / wsum * pes_s[myi];
            out[(size_t)NTOK * TOPK + (size_t)gt * TOPK + lane] = (float)myi;
            atomicAdd(&hist_s[myi], 1);
        }
    }

    __syncthreads();
    if (tid < NEXP)
        atomicAdd(&out[2 * NTOK * TOPK + tid], (float)hist_s[tid]);
}

extern "C" void kernel_launch(void* const* d_in, const int* in_sizes, int n_in,
                              void* d_out, int out_size) {
    const float* hs    = (const float*)d_in[0];   // [4,4096,2048] f32
    const float* scale = (const float*)d_in[1];   // [2048] f32
    const float* pw    = (const float*)d_in[2];   // [64,2048] f32
    const float* pes   = (const float*)d_in[3];   // [64] f32
    float* out = (float*)d_out;

    prep_kernel<<<(HID * NEXP) / 256, 256>>>(pw, scale, out);
    gemma4_router_kernel<<<NTOK / TPB, THREADS>>>(hs, pes, out);
}

// round 9
// speedup vs baseline: 1.8150x; 1.1065x over previous
#include <cuda_runtime.h>

#define HID   2048
#define NEXP  64
#define TOPK  8
#define TPB   64
#define KC    64
#define NCHUNK 32
#define THREADS 256
#define PADX  68          // xs row stride (floats)
#define NTOK  16384
#define RS_H  0.022097086912079612f   // 1/sqrt(2048)
#define EPSV  1e-6f

// prep-folded, pre-swizzled weights: [chunk][e*64 + (k ^ ((e>>2)<<2))]
__device__ float w_g[HID * NEXP];

#define CP16(dst_u32, src_ptr) \
    asm volatile("cp.async.ca.shared.global [%0], [%1], 16;" :: "r"(dst_u32), "l"(src_ptr))
#define CP_COMMIT() asm volatile("cp.async.commit_group;")
#define CP_WAIT0()  asm volatile("cp.async.wait_group 0;")

// smem layout (floats): xs0 | xs1 | ws0 | ws1 | ssq | pes | hist
#define OFF_XS0  0
#define OFF_XS1  (TPB * PADX)                 // 4352
#define OFF_WS0  (2 * TPB * PADX)             // 8704
#define OFF_WS1  (2 * TPB * PADX + KC * NEXP) // 12800
#define OFF_SSQ  (2 * TPB * PADX + 2 * KC * NEXP)   // 16896
#define OFF_PES  (OFF_SSQ + TPB)
#define OFF_HIST (OFF_PES + NEXP)
#define SMEM_FLOATS (OFF_HIST + NEXP)          // 17088 -> 68352 B

// prep: fold scale*RS_H into W, transpose to [k-chunk][expert][k], apply the
// smem XOR swizzle in GLOBAL layout so the main kernel cp.asyncs it verbatim.
// Also zero the expert-count tail of out.
__global__ void prep_kernel(const float* __restrict__ pw,
                            const float* __restrict__ scale,
                            float* __restrict__ out) {
    int o  = blockIdx.x * blockDim.x + threadIdx.x;  // 0..131071
    int ch = o >> 12;
    int e  = (o >> 6) & 63;
    int c  = o & 63;
    int k  = ch * KC + (c ^ ((e >> 2) << 2));        // undo swizzle -> source k
    w_g[o] = pw[(size_t)e * HID + k] * scale[k] * RS_H;
    if (o < NEXP) out[2 * NTOK * TOPK + o] = 0.0f;
}

__global__ __launch_bounds__(THREADS, 3)
void gemma4_router_kernel(const float* __restrict__ hs,
                          const float* __restrict__ pes,
                          float* __restrict__ out) {
    extern __shared__ float sm[];
    float* ssq_s  = sm + OFF_SSQ;
    float* pes_s  = sm + OFF_PES;
    int*   hist_s = (int*)(sm + OFF_HIST);

    const int tid  = threadIdx.x;
    const int tok0 = blockIdx.x * TPB;

    if (tid < NEXP) { pes_s[tid] = pes[tid]; hist_s[tid] = 0; }

    const int g  = tid >> 4;   // 0..15
    const int c4 = tid & 15;   // 0..15
    const int tt0 = g * 4;     // token tile base (round-2 mapping)
    const int ee0 = c4 * 4;    // expert tile base

    const unsigned xs_base[2] = {
        (unsigned)__cvta_generic_to_shared(sm + OFF_XS0),
        (unsigned)__cvta_generic_to_shared(sm + OFF_XS1) };
    const unsigned ws_base[2] = {
        (unsigned)__cvta_generic_to_shared(sm + OFF_WS0),
        (unsigned)__cvta_generic_to_shared(sm + OFF_WS1) };

    // async-copy one chunk into buffer b: x tile (64x64 -> PADX rows) + w tile (flat 4096)
    auto issue_chunk = [&](int ch, int b) {
        const float* xsrc = hs + (size_t)tok0 * HID + ch * KC;
        const float* wsrc = w_g + (size_t)ch * (KC * NEXP);
        #pragma unroll
        for (int j = 0; j < 4; j++) {
            int u   = tid + THREADS * j;          // 0..1023 16B units
            int row = u >> 4, seg = u & 15;
            CP16(xs_base[b] + (unsigned)(row * PADX + seg * 4) * 4,
                 xsrc + (size_t)row * HID + seg * 4);
            CP16(ws_base[b] + (unsigned)(u * 4) * 4, wsrc + u * 4);
        }
        CP_COMMIT();
    };

    issue_chunk(0, 0);

    float acc[4][4];
    #pragma unroll
    for (int a = 0; a < 4; a++)
        #pragma unroll
        for (int b = 0; b < 4; b++) acc[a][b] = 0.f;

    float ssq[4] = {0.f, 0.f, 0.f, 0.f};
    int swb[4];
    #pragma unroll
    for (int b = 0; b < 4; b++) swb[b] = ((ee0 + b) >> 2) << 2;

    for (int ch = 0; ch < NCHUNK; ch++) {
        const int cur = ch & 1;
        CP_WAIT0();
        __syncthreads();                 // chunk ready; everyone done with buf cur^1
        if (ch + 1 < NCHUNK) issue_chunk(ch + 1, cur ^ 1);

        const float* xs = sm + (cur ? OFF_XS1 : OFF_XS0);
        const float* ws = sm + (cur ? OFF_WS1 : OFF_WS0);

        // ssq: identical expression/order to round-2 staging (same values from smem)
        #pragma unroll
        for (int i = 0; i < 4; i++) {
            float4 xv = *(const float4*)&xs[(g + 16 * i) * PADX + c4 * 4];
            ssq[i] += xv.x * xv.x + xv.y * xv.y + xv.z * xv.z + xv.w * xv.w;
        }

        // GEMM: verbatim round-2 inner loop (bit-identical contraction)
        #pragma unroll
        for (int k = 0; k < KC; k += 4) {
            float4 xv[4], wv[4];
            #pragma unroll
            for (int a = 0; a < 4; a++)
                xv[a] = *(const float4*)&xs[(tt0 + a) * PADX + k];
            #pragma unroll
            for (int b = 0; b < 4; b++)
                wv[b] = *(const float4*)&ws[(ee0 + b) * KC + (k ^ swb[b])];
            #pragma unroll
            for (int a = 0; a < 4; a++)
                #pragma unroll
                for (int b = 0; b < 4; b++)
                    acc[a][b] += xv[a].x * wv[b].x + xv[a].y * wv[b].y
                               + xv[a].z * wv[b].z + xv[a].w * wv[b].w;
        }
        __syncthreads();                 // done reading buf cur (next iter overwrites)
    }

    // ---- per-token sum-of-squares reduction (identical to round-2) ----
    #pragma unroll
    for (int i = 0; i < 4; i++) {
        float v = ssq[i];
        v += __shfl_xor_sync(0xffffffffu, v, 1);
        v += __shfl_xor_sync(0xffffffffu, v, 2);
        v += __shfl_xor_sync(0xffffffffu, v, 4);
        v += __shfl_xor_sync(0xffffffffu, v, 8);
        if (c4 == 0) ssq_s[g + 16 * i] = v;
    }
    __syncthreads();

    // ---- RMS factor + write logits into xs0 ----
    float* xl = sm + OFF_XS0;
    float f[4];
    #pragma unroll
    for (int a = 0; a < 4; a++)
        f[a] = rsqrtf(ssq_s[tt0 + a] * (1.0f / HID) + EPSV);
    __syncthreads();
    #pragma unroll
    for (int a = 0; a < 4; a++)
        #pragma unroll
        for (int b = 0; b < 4; b++)
            xl[(tt0 + a) * PADX + ee0 + b] = acc[a][b] * f[a];
    __syncthreads();

    // ---- phase C: softmax + top-8 (one warp handles 8 tokens) ----
    const int wid = tid >> 5, lane = tid & 31;
    for (int t = wid * 8; t < wid * 8 + 8; t++) {
        float v0 = xl[t * PADX + lane];
        float v1 = xl[t * PADX + lane + 32];

        float m = fmaxf(v0, v1);
        #pragma unroll
        for (int s = 16; s > 0; s >>= 1)
            m = fmaxf(m, __shfl_xor_sync(0xffffffffu, m, s));

        float p0 = expf(v0 - m);
        float p1 = expf(v1 - m);
        float sum = p0 + p1;
        #pragma unroll
        for (int s = 16; s > 0; s >>= 1)
            sum += __shfl_xor_sync(0xffffffffu, sum, s);
        float inv = 1.0f / sum;
        p0 *= inv; p1 *= inv;

        float wsum = 0.f;
        float myv = 0.f; int myi = 0;
        #pragma unroll
        for (int r = 0; r < TOPK; r++) {
            float bv = p0; int bi = lane;
            if (p1 > bv) { bv = p1; bi = lane + 32; }
            #pragma unroll
            for (int s = 16; s > 0; s >>= 1) {
                float ov = __shfl_xor_sync(0xffffffffu, bv, s);
                int   oi = __shfl_xor_sync(0xffffffffu, bi, s);
                if (ov > bv || (ov == bv && oi < bi)) { bv = ov; bi = oi; }
            }
            wsum += bv;
            if (lane == r) { myv = bv; myi = bi; }
            if (bi == lane)            p0 = -1.f;
            else if (bi == lane + 32)  p1 = -1.f;
        }

        if (lane < TOPK) {
            int gt = tok0 + t;
            out[(size_t)gt * TOPK + lane] = myv / wsum * pes_s[myi];
            out[(size_t)NTOK * TOPK + (size_t)gt * TOPK + lane] = (float)myi;
            atomicAdd(&hist_s[myi], 1);
        }
    }

    __syncthreads();
    if (tid < NEXP)
        atomicAdd(&out[2 * NTOK * TOPK + tid], (float)hist_s[tid]);
}

extern "C" void kernel_launch(void* const* d_in, const int* in_sizes, int n_in,
                              void* d_out, int out_size) {
    const float* hs    = (const float*)d_in[0];   // [4,4096,2048] f32
    const float* scale = (const float*)d_in[1];   // [2048] f32
    const float* pw    = (const float*)d_in[2];   // [64,2048] f32
    const float* pes   = (const float*)d_in[3];   // [64] f32
    float* out = (float*)d_out;

    size_t smem_bytes = SMEM_FLOATS * sizeof(float);   // 68352 B
    cudaFuncSetAttribute(gemma4_router_kernel,
                         cudaFuncAttributeMaxDynamicSharedMemorySize,
                         (int)smem_bytes);

    prep_kernel<<<(HID * NEXP) / 256, 256>>>(pw, scale, out);
    gemma4_router_kernel<<<NTOK / TPB, THREADS, smem_bytes>>>(hs, pes, out);
}